// round 3
// baseline (speedup 1.0000x reference)
#include <cuda_runtime.h>
#include <cuda_bf16.h>

#define N_MAX   100000
#define E_MAX   1600000
#define F_IN    128
#define HID     16
#define D_OUT   128

// Scratch (float4 arrays guarantee 16B alignment for vector loads)
__device__ float          d_dinv[N_MAX];
__device__ float4         d_g1  [N_MAX * HID / 4];
__device__ float4         d_agg1[N_MAX * HID / 4];
__device__ float4         d_t   [N_MAX * HID / 4];
__device__ float4         d_agg2[N_MAX * HID / 4];
__device__ int            d_edges[2 * E_MAX];   // converted int32: [src | dst]
__device__ int            d_idx64;              // 1 if edge buffer is int64

// ---------------------------------------------------------------------------
// Detect index width: if the first 1024 int64 words are all in [0, n) the
// buffer is genuine int64; int32 data read as int64 has huge high words.
// ---------------------------------------------------------------------------
__global__ void k_detect(const long long* __restrict__ ei, int n) {
    if (blockIdx.x == 0 && threadIdx.x == 0) {
        int ok = 1;
        for (int i = 0; i < 1024; i++) {
            long long v = ei[i];
            if (v < 0 || v >= (long long)n) { ok = 0; break; }
        }
        d_idx64 = ok;
    }
}

// ---------------------------------------------------------------------------
// Convert edge indices to clamped int32 (handles both int32 / int64 input)
// ---------------------------------------------------------------------------
__global__ void k_cvt(const void* __restrict__ ei, int total, int n) {
    int i = blockIdx.x * blockDim.x + threadIdx.x;
    if (i >= total) return;
    long long v = d_idx64 ? ((const long long*)ei)[i]
                          : (long long)((const int*)ei)[i];
    d_edges[i] = (v < 0) ? 0 : (v >= n ? n - 1 : (int)v);
}

// ---------------------------------------------------------------------------
// Degree: deg[i] = 1 (self loop) + #edges with dst==i ; then dinv = rsqrt(deg)
// ---------------------------------------------------------------------------
__global__ void k_deg_init(int n) {
    int i = blockIdx.x * blockDim.x + threadIdx.x;
    if (i < n) d_dinv[i] = 1.0f;
}

__global__ void k_deg_count(int e, int E) {
    int i = blockIdx.x * blockDim.x + threadIdx.x;
    if (i < e) atomicAdd(&d_dinv[d_edges[E + i]], 1.0f);
}

__global__ void k_rsqrt(int n) {
    int i = blockIdx.x * blockDim.x + threadIdx.x;
    if (i < n) d_dinv[i] = rsqrtf(d_dinv[i]);
}

// ---------------------------------------------------------------------------
// GEMM1: g1[i][k] = (x[i] @ W1[:,k]) * dinv[i]; agg1 initialized = g1 (self loop)
// block = 256 threads, tile = 16 nodes (16 threads per node, one per hidden k)
// ---------------------------------------------------------------------------
__global__ void k_gemm1(const float* __restrict__ x,
                        const float* __restrict__ W1, int n) {
    __shared__ float W1s[F_IN * HID];   // 8 KB
    __shared__ float xs[16][F_IN];      // 8 KB
    for (int i = threadIdx.x; i < F_IN * HID; i += 256) W1s[i] = W1[i];

    int ln = threadIdx.x >> 4;          // local node 0..15
    int k  = threadIdx.x & 15;          // hidden index
    int ntiles = (n + 15) >> 4;
    float* g1   = reinterpret_cast<float*>(d_g1);
    float* agg1 = reinterpret_cast<float*>(d_agg1);

    for (int tile = blockIdx.x; tile < ntiles; tile += gridDim.x) {
        int base = tile << 4;
        __syncthreads();
        for (int i = threadIdx.x; i < 16 * F_IN; i += 256) {
            int r = i >> 7, c = i & 127;
            int node = base + r;
            xs[r][c] = (node < n) ? x[(size_t)node * F_IN + c] : 0.0f;
        }
        __syncthreads();
        int node = base + ln;
        if (node < n) {
            float acc = 0.0f;
            #pragma unroll
            for (int c = 0; c < F_IN; c++)
                acc += xs[ln][c] * W1s[c * HID + k];
            float v = acc * d_dinv[node];
            g1  [node * HID + k] = v;
            agg1[node * HID + k] = v;
        }
    }
}

// ---------------------------------------------------------------------------
// Edge scatter in 16-dim space: agg[dst] += g[src]. 4 threads per edge,
// each handles one float4 (16B) slice. LAYER selects buffer pair.
// ---------------------------------------------------------------------------
template <int LAYER>
__global__ void k_edge16(int e, int E) {
    int gid = blockIdx.x * blockDim.x + threadIdx.x;
    int ed  = gid >> 2;
    if (ed >= e) return;
    int q = (gid & 3) << 2;

    const float* g   = (LAYER == 0) ? reinterpret_cast<const float*>(d_g1)
                                    : reinterpret_cast<const float*>(d_t);
    float*       agg = (LAYER == 0) ? reinterpret_cast<float*>(d_agg1)
                                    : reinterpret_cast<float*>(d_agg2);

    int s = __ldg(&d_edges[ed]);
    int d = __ldg(&d_edges[E + ed]);
    float4 v = *reinterpret_cast<const float4*>(g + (size_t)s * HID + q);
    float* p = agg + (size_t)d * HID + q;
    atomicAdd(p + 0, v.x);
    atomicAdd(p + 1, v.y);
    atomicAdd(p + 2, v.z);
    atomicAdd(p + 3, v.w);
}

// ---------------------------------------------------------------------------
// Mid: t = relu(agg1*dinv + b1) * dinv ; agg2 initialized = t (self loop)
// ---------------------------------------------------------------------------
__global__ void k_mid(const float* __restrict__ b1, int n) {
    int idx = blockIdx.x * blockDim.x + threadIdx.x;
    if (idx >= n * HID) return;
    int i = idx >> 4, k = idx & 15;
    const float* agg1 = reinterpret_cast<const float*>(d_agg1);
    float* t    = reinterpret_cast<float*>(d_t);
    float* agg2 = reinterpret_cast<float*>(d_agg2);
    float dv = d_dinv[i];
    float v  = fmaxf(agg1[idx] * dv + b1[k], 0.0f) * dv;
    t[idx]    = v;
    agg2[idx] = v;
}

// ---------------------------------------------------------------------------
// GEMM2 + epilogue: out[i][j] = relu((agg2[i]*dinv[i]) @ W2[:,j] + b2[j])
// block = 512 threads, tile = 4 nodes (128 threads per node, one per out col)
// ---------------------------------------------------------------------------
__global__ void k_gemm2(const float* __restrict__ W2,
                        const float* __restrict__ b2,
                        float* __restrict__ out, int n) {
    __shared__ float W2s[HID * D_OUT];  // 8 KB
    __shared__ float ts[4][HID];
    for (int i = threadIdx.x; i < HID * D_OUT; i += 512) W2s[i] = W2[i];

    int ln = threadIdx.x >> 7;          // local node 0..3
    int j  = threadIdx.x & 127;         // output column
    float bj = b2[j];
    int ntiles = (n + 3) >> 2;
    const float* agg2 = reinterpret_cast<const float*>(d_agg2);

    for (int tile = blockIdx.x; tile < ntiles; tile += gridDim.x) {
        int base = tile << 2;
        __syncthreads();
        if (threadIdx.x < 64) {
            int r = threadIdx.x >> 4, c = threadIdx.x & 15;
            int node = base + r;
            ts[r][c] = (node < n) ? agg2[node * HID + c] * d_dinv[node] : 0.0f;
        }
        __syncthreads();
        int node = base + ln;
        if (node < n) {
            float acc = bj;
            #pragma unroll
            for (int c = 0; c < HID; c++)
                acc += ts[ln][c] * W2s[c * D_OUT + j];
            out[(size_t)node * D_OUT + j] = fmaxf(acc, 0.0f);
        }
    }
}

// ---------------------------------------------------------------------------
// Launch — inputs identified by SIZE, not position (robust to metadata order)
// ---------------------------------------------------------------------------
extern "C" void kernel_launch(void* const* d_in, const int* in_sizes, int n_in,
                              void* d_out, int out_size) {
    int ix = 0;
    for (int i = 1; i < n_in; i++) if (in_sizes[i] > in_sizes[ix]) ix = i;
    int ie = -1;
    for (int i = 0; i < n_in; i++) {
        if (i == ix) continue;
        if (ie < 0 || in_sizes[i] > in_sizes[ie]) ie = i;
    }
    int ib1 = -1, ib2 = -1, iw1 = -1, iw2 = -1;
    for (int i = 0; i < n_in; i++) {
        if (i == ix || i == ie) continue;
        if (in_sizes[i] == 16)       ib1 = i;
        else if (in_sizes[i] == 128) ib2 = i;
        else if (iw1 < 0)            iw1 = i;
        else                         iw2 = i;
    }

    const float* x   = (const float*)d_in[ix];
    const void*  ei  = d_in[ie];
    const float* W1  = (const float*)d_in[iw1];
    const float* b1  = (const float*)d_in[ib1];
    const float* W2  = (const float*)d_in[iw2];
    const float* b2  = (const float*)d_in[ib2];
    float*       out = (float*)d_out;

    int N = in_sizes[ix] / F_IN;    // 100000
    int E = in_sizes[ie] / 2;       // 1600000

    k_detect<<<1, 1>>>((const long long*)ei, N);
    k_cvt<<<(2 * E + 255) / 256, 256>>>(ei, 2 * E, N);

    k_deg_init <<<(N + 255) / 256, 256>>>(N);
    k_deg_count<<<(E + 255) / 256, 256>>>(E, E);
    k_rsqrt    <<<(N + 255) / 256, 256>>>(N);

    k_gemm1<<<1480, 256>>>(x, W1, N);

    int egrid = (4 * E + 255) / 256;
    k_edge16<0><<<egrid, 256>>>(E, E);

    k_mid<<<(N * HID + 255) / 256, 256>>>(b1, N);

    k_edge16<1><<<egrid, 256>>>(E, E);

    k_gemm2<<<1480, 512>>>(W2, b2, out, N);
}

// round 4
// speedup vs baseline: 1.3843x; 1.3843x over previous
#include <cuda_runtime.h>
#include <cuda_bf16.h>

#define N_MAX   100000
#define E_MAX   1600000
#define F_IN    128
#define HID     16
#define D_OUT   128

// Scratch (float4 arrays guarantee 16B alignment for vector loads)
__device__ float          d_dinv[N_MAX];
__device__ float4         d_g1  [N_MAX * HID / 4];
__device__ float4         d_agg1[N_MAX * HID / 4];
__device__ float4         d_t   [N_MAX * HID / 4];
__device__ float4         d_agg2[N_MAX * HID / 4];
__device__ int2           d_edge2[E_MAX];   // converted & clamped (src, dst)
__device__ int            d_idx64;          // 1 if edge buffer is int64

// ---------------------------------------------------------------------------
// Detect index width (parallel): if the first 1024 int64 words are all in
// [0, n) the buffer is genuine int64; int32 data read as int64 has huge
// high words (P(false positive) ~ 1e-5 per word).
// ---------------------------------------------------------------------------
__global__ void k_detect(const long long* __restrict__ ei, int n) {
    __shared__ int ok;
    if (threadIdx.x == 0) ok = 1;
    __syncthreads();
    long long v = ei[threadIdx.x];
    if (v < 0 || v >= (long long)n) ok = 0;   // benign race, all write 0
    __syncthreads();
    if (threadIdx.x == 0) d_idx64 = ok;
}

// ---------------------------------------------------------------------------
// d_dinv init to 1.0 (self loop)
// ---------------------------------------------------------------------------
__global__ void k_deg_init(int n) {
    int i = blockIdx.x * blockDim.x + threadIdx.x;
    if (i < n) d_dinv[i] = 1.0f;
}

// ---------------------------------------------------------------------------
// Fused convert + degree count: one thread per edge reads (src, dst) in the
// detected width, clamps, writes interleaved int2, and bumps deg[dst].
// ---------------------------------------------------------------------------
__global__ void k_cvt_deg(const void* __restrict__ ei, int e, int n) {
    int i = blockIdx.x * blockDim.x + threadIdx.x;
    if (i >= e) return;
    long long sv, dv;
    if (d_idx64) {
        const long long* p = (const long long*)ei;
        sv = p[i]; dv = p[e + i];
    } else {
        const int* p = (const int*)ei;
        sv = p[i]; dv = p[e + i];
    }
    int2 pr;
    pr.x = (sv < 0) ? 0 : (sv >= n ? n - 1 : (int)sv);
    pr.y = (dv < 0) ? 0 : (dv >= n ? n - 1 : (int)dv);
    d_edge2[i] = pr;
    atomicAdd(&d_dinv[pr.y], 1.0f);
}

__global__ void k_rsqrt(int n) {
    int i = blockIdx.x * blockDim.x + threadIdx.x;
    if (i < n) d_dinv[i] = rsqrtf(d_dinv[i]);
}

// ---------------------------------------------------------------------------
// GEMM1: g1[i][k] = (x[i] @ W1[:,k]) * dinv[i]; agg1 initialized = g1 (self loop)
// block = 256 threads, tile = 16 nodes (16 threads per node, one per hidden k)
// ---------------------------------------------------------------------------
__global__ void k_gemm1(const float* __restrict__ x,
                        const float* __restrict__ W1, int n) {
    __shared__ float W1s[F_IN * HID];   // 8 KB
    __shared__ float xs[16][F_IN];      // 8 KB
    for (int i = threadIdx.x; i < F_IN * HID; i += 256) W1s[i] = W1[i];

    int ln = threadIdx.x >> 4;          // local node 0..15
    int k  = threadIdx.x & 15;          // hidden index
    int ntiles = (n + 15) >> 4;
    float* g1   = reinterpret_cast<float*>(d_g1);
    float* agg1 = reinterpret_cast<float*>(d_agg1);

    for (int tile = blockIdx.x; tile < ntiles; tile += gridDim.x) {
        int base = tile << 4;
        __syncthreads();
        for (int i = threadIdx.x; i < 16 * F_IN; i += 256) {
            int r = i >> 7, c = i & 127;
            int node = base + r;
            xs[r][c] = (node < n) ? x[(size_t)node * F_IN + c] : 0.0f;
        }
        __syncthreads();
        int node = base + ln;
        if (node < n) {
            float acc = 0.0f;
            #pragma unroll
            for (int c = 0; c < F_IN; c++)
                acc += xs[ln][c] * W1s[c * HID + k];
            float v = acc * d_dinv[node];
            g1  [node * HID + k] = v;
            agg1[node * HID + k] = v;
        }
    }
}

// ---------------------------------------------------------------------------
// Edge scatter in 16-dim space: agg[dst] += g[src]. 4 threads per edge,
// each handles one float4 (16B) slice via a single vectorized RED.
// ---------------------------------------------------------------------------
template <int LAYER>
__global__ void k_edge16(int e) {
    int gid = blockIdx.x * blockDim.x + threadIdx.x;
    int ed  = gid >> 2;
    if (ed >= e) return;
    int q = (gid & 3) << 2;

    const float* g   = (LAYER == 0) ? reinterpret_cast<const float*>(d_g1)
                                    : reinterpret_cast<const float*>(d_t);
    float*       agg = (LAYER == 0) ? reinterpret_cast<float*>(d_agg1)
                                    : reinterpret_cast<float*>(d_agg2);

    int2 p = __ldg(&d_edge2[ed]);   // 4 lanes of an edge hit same addr (bcast)
    float4 v = *reinterpret_cast<const float4*>(g + (size_t)p.x * HID + q);
    float* a = agg + (size_t)p.y * HID + q;
    asm volatile("red.global.add.v4.f32 [%0], {%1, %2, %3, %4};"
                 :: "l"(a), "f"(v.x), "f"(v.y), "f"(v.z), "f"(v.w)
                 : "memory");
}

// ---------------------------------------------------------------------------
// Mid: t = relu(agg1*dinv + b1) * dinv ; agg2 initialized = t (self loop)
// ---------------------------------------------------------------------------
__global__ void k_mid(const float* __restrict__ b1, int n) {
    int idx = blockIdx.x * blockDim.x + threadIdx.x;
    if (idx >= n * HID) return;
    int i = idx >> 4, k = idx & 15;
    const float* agg1 = reinterpret_cast<const float*>(d_agg1);
    float* t    = reinterpret_cast<float*>(d_t);
    float* agg2 = reinterpret_cast<float*>(d_agg2);
    float dv = d_dinv[i];
    float v  = fmaxf(agg1[idx] * dv + b1[k], 0.0f) * dv;
    t[idx]    = v;
    agg2[idx] = v;
}

// ---------------------------------------------------------------------------
// GEMM2 + epilogue: out[i][j] = relu((agg2[i]*dinv[i]) @ W2[:,j] + b2[j])
// block = 512 threads, tile = 4 nodes (128 threads per node, one per out col)
// ---------------------------------------------------------------------------
__global__ void k_gemm2(const float* __restrict__ W2,
                        const float* __restrict__ b2,
                        float* __restrict__ out, int n) {
    __shared__ float W2s[HID * D_OUT];  // 8 KB
    __shared__ float ts[4][HID];
    for (int i = threadIdx.x; i < HID * D_OUT; i += 512) W2s[i] = W2[i];

    int ln = threadIdx.x >> 7;          // local node 0..3
    int j  = threadIdx.x & 127;         // output column
    float bj = b2[j];
    int ntiles = (n + 3) >> 2;
    const float* agg2 = reinterpret_cast<const float*>(d_agg2);

    for (int tile = blockIdx.x; tile < ntiles; tile += gridDim.x) {
        int base = tile << 2;
        __syncthreads();
        if (threadIdx.x < 64) {
            int r = threadIdx.x >> 4, c = threadIdx.x & 15;
            int node = base + r;
            ts[r][c] = (node < n) ? agg2[node * HID + c] * d_dinv[node] : 0.0f;
        }
        __syncthreads();
        int node = base + ln;
        if (node < n) {
            float acc = bj;
            #pragma unroll
            for (int c = 0; c < HID; c++)
                acc += ts[ln][c] * W2s[c * D_OUT + j];
            out[(size_t)node * D_OUT + j] = fmaxf(acc, 0.0f);
        }
    }
}

// ---------------------------------------------------------------------------
// Launch — inputs identified by SIZE, not position (robust to metadata order)
// ---------------------------------------------------------------------------
extern "C" void kernel_launch(void* const* d_in, const int* in_sizes, int n_in,
                              void* d_out, int out_size) {
    int ix = 0;
    for (int i = 1; i < n_in; i++) if (in_sizes[i] > in_sizes[ix]) ix = i;
    int ie = -1;
    for (int i = 0; i < n_in; i++) {
        if (i == ix) continue;
        if (ie < 0 || in_sizes[i] > in_sizes[ie]) ie = i;
    }
    int ib1 = -1, ib2 = -1, iw1 = -1, iw2 = -1;
    for (int i = 0; i < n_in; i++) {
        if (i == ix || i == ie) continue;
        if (in_sizes[i] == 16)       ib1 = i;
        else if (in_sizes[i] == 128) ib2 = i;
        else if (iw1 < 0)            iw1 = i;
        else                         iw2 = i;
    }

    const float* x   = (const float*)d_in[ix];
    const void*  ei  = d_in[ie];
    const float* W1  = (const float*)d_in[iw1];
    const float* b1  = (const float*)d_in[ib1];
    const float* W2  = (const float*)d_in[iw2];
    const float* b2  = (const float*)d_in[ib2];
    float*       out = (float*)d_out;

    int N = in_sizes[ix] / F_IN;    // 100000
    int E = in_sizes[ie] / 2;       // 1600000

    k_deg_init<<<(N + 255) / 256, 256>>>(N);
    k_detect  <<<1, 1024>>>((const long long*)ei, N);
    k_cvt_deg <<<(E + 255) / 256, 256>>>(ei, E, N);
    k_rsqrt   <<<(N + 255) / 256, 256>>>(N);

    k_gemm1<<<1480, 256>>>(x, W1, N);

    int egrid = (4 * E + 255) / 256;
    k_edge16<0><<<egrid, 256>>>(E);

    k_mid<<<(N * HID + 255) / 256, 256>>>(b1, N);

    k_edge16<1><<<egrid, 256>>>(E);

    k_gemm2<<<1480, 512>>>(W2, b2, out, N);
}